// round 1
// baseline (speedup 1.0000x reference)
#include <cuda_runtime.h>

#define NPT   256      // points per block == threads per block
#define DIM   65
#define NA    16
#define ASTR  68       // floats per anchor smem row (16B-aligned stride)
#define ALPHA 0.1f
#define EPSF  1e-7f

typedef unsigned long long u64;

// ---- f32x2 packed helpers (sm_103a) ----
__device__ __forceinline__ u64 pk(float lo, float hi) {
    u64 r; asm("mov.b64 %0, {%1,%2};" : "=l"(r) : "f"(lo), "f"(hi)); return r;
}
__device__ __forceinline__ void upk(u64 v, float& lo, float& hi) {
    asm("mov.b64 {%0,%1}, %2;" : "=f"(lo), "=f"(hi) : "l"(v));
}
__device__ __forceinline__ u64 ffma2(u64 a, u64 b, u64 c) {
    u64 d; asm("fma.rn.f32x2 %0, %1, %2, %3;" : "=l"(d) : "l"(a), "l"(b), "l"(c)); return d;
}
__device__ __forceinline__ u64 fmul2(u64 a, u64 b) {
    u64 d; asm("mul.rn.f32x2 %0, %1, %2;" : "=l"(d) : "l"(a), "l"(b)); return d;
}

__global__ __launch_bounds__(NPT, 2)
void hfh_kernel(const float* __restrict__ hyp, const float* __restrict__ anchors,
                float* __restrict__ out, int B)
{
    extern __shared__ float smem[];
    float* tile = smem;                  // NPT*DIM floats (point tile, row stride 65 -> conflict-free)
    float* anch = smem + NPT * DIM;      // NA*ASTR floats: [s0..s63, a_t, -a_t, pad, pad]

    const int tid = threadIdx.x;
    const long long p0 = (long long)blockIdx.x * NPT;
    const int n = min(NPT, B - (int)p0);

    // ---- Stage point tile (coalesced float4 when full) ----
    const float* src = hyp + p0 * DIM;
    if (n == NPT) {
        const float4* s4 = (const float4*)src;
        float4* t4 = (float4*)tile;
        #pragma unroll 4
        for (int i = tid; i < NPT * DIM / 4; i += NPT) t4[i] = s4[i];
    } else {
        for (int i = tid; i < n * DIM; i += NPT) tile[i] = src[i];
    }

    // ---- Anchor prep: recompute a_t = sqrt(1 + |s|^2) (== reference proj) ----
    if (tid < NA) {
        float* ar = anch + tid * ASTR;
        const float* ga = anchors + tid * DIM + 1;
        float ss = 0.f;
        #pragma unroll
        for (int k = 0; k < 64; k++) { float v = ga[k]; ar[k] = v; ss = fmaf(v, v, ss); }
        float at = sqrtf(1.0f + ss);
        ar[64] = at;   // +a_t  (for u / out)
        ar[65] = -at;  // -a_t  (folded sign for Minkowski inner)
        ar[66] = 0.f; ar[67] = 0.f;
    }
    __syncthreads();

    if (tid < n) {
        const float* row = tile + tid * DIM;
        float h0 = row[0];
        u64 hp[32];
        #pragma unroll
        for (int j = 0; j < 32; j++) hp[j] = pk(row[1 + 2 * j], row[2 + 2 * j]);

        // ---- 16 Minkowski inners; track first-min of clamped z (== argmin of dists) ----
        float best_z = 3.4e38f, best_inner = 0.f;
        int best_a = 0;
        #pragma unroll 1
        for (int a = 0; a < NA; a++) {
            const ulonglong2* av = (const ulonglong2*)(anch + a * ASTR);
            u64 accA = pk(h0 * anch[a * ASTR + 65], 0.f);  // -h0*a_t seeded
            u64 accB = pk(0.f, 0.f);
            #pragma unroll
            for (int j = 0; j < 16; j++) {
                ulonglong2 v = av[j];                       // LDS.128 broadcast
                accA = ffma2(hp[2 * j],     v.x, accA);
                accB = ffma2(hp[2 * j + 1], v.y, accB);
            }
            float x0, x1, y0, y1; upk(accA, x0, x1); upk(accB, y0, y1);
            float inner = (x0 + x1) + (y0 + y1);
            float z = fmaxf(-inner, 1.0f + EPSF);
            if (z < best_z) { best_z = z; best_inner = inner; best_a = a; }
        }

        // ---- Epilogue (all scalars from the nearest anchor) ----
        const float xy = best_inner;
        const float d  = acoshf(best_z);                    // acosh(max(-xy, 1+eps))
        const ulonglong2* av = (const ulonglong2*)(anch + best_a * ASTR);
        const float at = anch[best_a * ASTR + 64];

        // uu = linner(u,u), u = na + xy*h  (computed elementwise like the reference)
        u64 xy2 = pk(xy, xy);
        float u0 = fmaf(xy, h0, at);
        u64 accA = pk(-u0 * u0, 0.f), accB = pk(0.f, 0.f);
        #pragma unroll
        for (int j = 0; j < 16; j++) {
            ulonglong2 v = av[j];
            u64 uL = ffma2(xy2, hp[2 * j],     v.x);
            u64 uH = ffma2(xy2, hp[2 * j + 1], v.y);
            accA = ffma2(uL, uL, accA);
            accB = ffma2(uH, uH, accB);
        }
        float x0, x1, y0, y1; upk(accA, x0, x1); upk(accB, y0, y1);
        float uu = (x0 + x1) + (y0 + y1);

        float unorm = sqrtf(fmaxf(uu, EPSF));
        float scale = (ALPHA * d) / unorm;
        float vv = scale * scale * uu;                       // linner(v,v)
        float vn = sqrtf(fmaxf(vv, EPSF * EPSF));
        float sinhc = (vn > EPSF) ? (sinhf(vn) / vn) : 1.0f;
        float ch = coshf(vn);
        float s2 = sinhc * scale;
        float c1 = fmaf(s2, xy, ch);                         // out = c1*h + s2*na

        float* wrow = tile + tid * DIM;                      // overwrite own row in-place
        wrow[0] = fmaf(c1, h0, s2 * at);
        u64 c1v = pk(c1, c1), s2v = pk(s2, s2);
        #pragma unroll
        for (int j = 0; j < 16; j++) {
            ulonglong2 v = av[j];
            u64 oL = ffma2(c1v, hp[2 * j],     fmul2(s2v, v.x));
            u64 oH = ffma2(c1v, hp[2 * j + 1], fmul2(s2v, v.y));
            float a0, a1, b0, b1; upk(oL, a0, a1); upk(oH, b0, b1);
            wrow[1 + 4 * j] = a0; wrow[2 + 4 * j] = a1;
            wrow[3 + 4 * j] = b0; wrow[4 + 4 * j] = b1;
        }
    }
    __syncthreads();

    // ---- Coalesced writeout ----
    float* dst = out + p0 * DIM;
    if (n == NPT) {
        float4* d4 = (float4*)dst;
        const float4* t4 = (const float4*)tile;
        #pragma unroll 4
        for (int i = tid; i < NPT * DIM / 4; i += NPT) d4[i] = t4[i];
    } else {
        for (int i = tid; i < n * DIM; i += NPT) dst[i] = tile[i];
    }
}

extern "C" void kernel_launch(void* const* d_in, const int* in_sizes, int n_in,
                              void* d_out, int out_size)
{
    const float* hyp = (const float*)d_in[0];
    const float* anc = (const float*)d_in[1];
    float* out = (float*)d_out;
    const int B = in_sizes[0] / DIM;
    const int grid = (B + NPT - 1) / NPT;
    const size_t shmem = (size_t)(NPT * DIM + NA * ASTR) * sizeof(float);  // 70,912 B
    cudaFuncSetAttribute(hfh_kernel, cudaFuncAttributeMaxDynamicSharedMemorySize, (int)shmem);
    hfh_kernel<<<grid, NPT, shmem>>>(hyp, anc, out, B);
}

// round 4
// speedup vs baseline: 1.3275x; 1.3275x over previous
#include <cuda_runtime.h>

#define NPT   256
#define DIM   65
#define NA    16
#define ASTR  68
#define ALPHA 0.1f
#define EPSF  1e-7f

typedef unsigned long long u64;

// ---- f32x2 packed helpers (sm_103a) ----
__device__ __forceinline__ u64 pk(float lo, float hi) {
    u64 r; asm("mov.b64 %0, {%1,%2};" : "=l"(r) : "f"(lo), "f"(hi)); return r;
}
__device__ __forceinline__ void upk(u64 v, float& lo, float& hi) {
    asm("mov.b64 {%0,%1}, %2;" : "=f"(lo), "=f"(hi) : "l"(v));
}
__device__ __forceinline__ u64 ffma2(u64 a, u64 b, u64 c) {
    u64 d; asm("fma.rn.f32x2 %0, %1, %2, %3;" : "=l"(d) : "l"(a), "l"(b), "l"(c)); return d;
}
__device__ __forceinline__ u64 fmul2(u64 a, u64 b) {
    u64 d; asm("mul.rn.f32x2 %0, %1, %2;" : "=l"(d) : "l"(a), "l"(b)); return d;
}
__device__ __forceinline__ unsigned s2u(const void* p) {
    unsigned a;
    asm("{ .reg .u64 t; cvta.to.shared.u64 t, %1; cvt.u32.u64 %0, t; }" : "=r"(a) : "l"(p));
    return a;
}

#define TILE_BYTES (NPT * DIM * 4)   // 66560, %16 == 0

__global__ __launch_bounds__(NPT, 2)
void hfh_kernel(const float* __restrict__ hyp, const float* __restrict__ anchors,
                float* __restrict__ out, int B)
{
    extern __shared__ float smem[];
    float* tile = smem;                       // NPT*DIM floats, row stride 65 (conflict-free)
    float* anch = smem + NPT * DIM;           // NA*ASTR floats: [s0..s63, a_t, -a_t, pad, pad]
    u64*   mbar = (u64*)(smem + NPT * DIM + NA * ASTR);

    const int tid = threadIdx.x;
    const long long p0 = (long long)blockIdx.x * NPT;
    const int n = min(NPT, B - (int)p0);
    const bool full = (n == NPT);
    const unsigned tile_sm = s2u(tile);
    const unsigned mbar_sm = s2u(mbar);

    // ---- Start async tile load (full blocks) ----
    if (full) {
        if (tid == 0) {
            asm volatile("mbarrier.init.shared.b64 [%0], %1;" :: "r"(mbar_sm), "r"(1) : "memory");
        }
        __syncthreads();
        if (tid == 0) {
            asm volatile("mbarrier.arrive.expect_tx.shared.b64 _, [%0], %1;"
                         :: "r"(mbar_sm), "r"(TILE_BYTES) : "memory");
            asm volatile("cp.async.bulk.shared::cta.global.mbarrier::complete_tx::bytes "
                         "[%0], [%1], %2, [%3];"
                         :: "r"(tile_sm), "l"(hyp + p0 * DIM), "r"(TILE_BYTES), "r"(mbar_sm)
                         : "memory");
        }
    } else {
        const float* src = hyp + p0 * DIM;
        for (int i = tid; i < n * DIM; i += NPT) tile[i] = src[i];
    }

    // ---- Anchor prep overlapped with the TMA load ----
    if (tid < NA) {
        float* ar = anch + tid * ASTR;
        const float* ga = anchors + tid * DIM + 1;
        float ss = 0.f;
        #pragma unroll
        for (int k = 0; k < 64; k++) { float v = ga[k]; ar[k] = v; ss = fmaf(v, v, ss); }
        float at = sqrtf(1.0f + ss);
        ar[64] = at; ar[65] = -at; ar[66] = 0.f; ar[67] = 0.f;
    }
    __syncthreads();                           // anchors (and scalar-path tile) visible

    if (full) {                                // wait for bulk tile
        asm volatile(
            "{\n\t.reg .pred P;\n\t"
            "WL_%=:\n\t"
            "mbarrier.try_wait.parity.acquire.cta.shared::cta.b64 P, [%0], 0, 0x989680;\n\t"
            "@P bra.uni WD_%=;\n\t"
            "bra.uni WL_%=;\n\t"
            "WD_%=:\n\t}"
            :: "r"(mbar_sm) : "memory");
    }

    if (tid < n) {
        float* row = tile + tid * DIM;
        const float h0 = row[0];
        u64 hp[32];
        #pragma unroll
        for (int j = 0; j < 32; j++) hp[j] = pk(row[1 + 2 * j], row[2 + 2 * j]);

        // ---- 16 Minkowski inners; first-min over clamped z == reference argmin ----
        float best_z = 3.4e38f, best_inner = 0.f;
        int best_a = 0;
        #pragma unroll 4
        for (int a = 0; a < NA; a++) {
            const float* base = anch + a * ASTR;
            const ulonglong2* av = (const ulonglong2*)base;
            u64 acc0 = pk(h0 * base[65], 0.f);          // seed with -h0*a_t
            u64 acc1 = pk(0.f, 0.f), acc2 = acc1, acc3 = acc1;
            #pragma unroll
            for (int j = 0; j < 16; j += 2) {
                ulonglong2 v0 = av[j];
                ulonglong2 v1 = av[j + 1];
                acc0 = ffma2(hp[2 * j],     v0.x, acc0);
                acc1 = ffma2(hp[2 * j + 1], v0.y, acc1);
                acc2 = ffma2(hp[2 * j + 2], v1.x, acc2);
                acc3 = ffma2(hp[2 * j + 3], v1.y, acc3);
            }
            float a0, a1, b0, b1, c0, c1x, d0, d1;
            upk(acc0, a0, a1); upk(acc1, b0, b1); upk(acc2, c0, c1x); upk(acc3, d0, d1);
            float inner = ((a0 + a1) + (b0 + b1)) + ((c0 + c1x) + (d0 + d1));
            float z = fmaxf(-inner, 1.0f + EPSF);
            if (z < best_z) { best_z = z; best_inner = inner; best_a = a; }
        }

        // ---- Epilogue; uu = linner(u,u) = xy^2 - 1 analytically ----
        const float xy = best_inner;
        const float d  = acoshf(best_z);
        const float* bb = anch + best_a * ASTR;
        const ulonglong2* av = (const ulonglong2*)bb;
        const float at = bb[64];

        float uu = fmaf(xy, xy, -1.0f);
        float unorm = sqrtf(fmaxf(uu, EPSF));
        float scale = (ALPHA * d) / unorm;
        float vv = scale * scale * uu;
        float vn = sqrtf(fmaxf(vv, EPSF * EPSF));
        float sinhc = (vn > EPSF) ? (sinhf(vn) / vn) : 1.0f;
        float ch = coshf(vn);
        float s2 = sinhc * scale;
        float c1 = fmaf(s2, xy, ch);            // out = c1*h + s2*na

        row[0] = fmaf(c1, h0, s2 * at);
        u64 c1v = pk(c1, c1), s2v = pk(s2, s2);
        #pragma unroll
        for (int j = 0; j < 16; j++) {
            ulonglong2 v = av[j];
            u64 oL = ffma2(c1v, hp[2 * j],     fmul2(s2v, v.x));
            u64 oH = ffma2(c1v, hp[2 * j + 1], fmul2(s2v, v.y));
            float a0, a1, b0, b1; upk(oL, a0, a1); upk(oH, b0, b1);
            row[1 + 4 * j] = a0; row[2 + 4 * j] = a1;
            row[3 + 4 * j] = b0; row[4 + 4 * j] = b1;
        }
    }
    __syncthreads();

    // ---- Bulk writeout ----
    if (full) {
        if (tid == 0) {
            asm volatile("fence.proxy.async.shared::cta;" ::: "memory");
            asm volatile("cp.async.bulk.global.shared::cta.bulk_group [%0], [%1], %2;"
                         :: "l"(out + p0 * DIM), "r"(tile_sm), "r"(TILE_BYTES) : "memory");
            asm volatile("cp.async.bulk.commit_group;" ::: "memory");
            asm volatile("cp.async.bulk.wait_group 0;" ::: "memory");
        }
    } else {
        float* dst = out + p0 * DIM;
        for (int i = tid; i < n * DIM; i += NPT) dst[i] = tile[i];
    }
}

extern "C" void kernel_launch(void* const* d_in, const int* in_sizes, int n_in,
                              void* d_out, int out_size)
{
    const float* hyp = (const float*)d_in[0];
    const float* anc = (const float*)d_in[1];
    float* out = (float*)d_out;
    const int B = in_sizes[0] / DIM;
    const int grid = (B + NPT - 1) / NPT;
    const size_t shmem = (size_t)(NPT * DIM + NA * ASTR) * sizeof(float) + 16;
    cudaFuncSetAttribute(hfh_kernel, cudaFuncAttributeMaxDynamicSharedMemorySize, (int)shmem);
    hfh_kernel<<<grid, NPT, shmem>>>(hyp, anc, out, B);
}

// round 6
// speedup vs baseline: 1.3730x; 1.0343x over previous
#include <cuda_runtime.h>

#define NPT   256
#define DIM   65
#define NA    16
#define ASTR  68
#define ALPHA 0.1f
#define EPSF  1e-7f

typedef unsigned long long u64;

// ---- f32x2 packed helpers (sm_103a) ----
__device__ __forceinline__ u64 pk(float lo, float hi) {
    u64 r; asm("mov.b64 %0, {%1,%2};" : "=l"(r) : "f"(lo), "f"(hi)); return r;
}
__device__ __forceinline__ void upk(u64 v, float& lo, float& hi) {
    asm("mov.b64 {%0,%1}, %2;" : "=f"(lo), "=f"(hi) : "l"(v));
}
__device__ __forceinline__ u64 ffma2(u64 a, u64 b, u64 c) {
    u64 d; asm("fma.rn.f32x2 %0, %1, %2, %3;" : "=l"(d) : "l"(a), "l"(b), "l"(c)); return d;
}
__device__ __forceinline__ u64 fmul2(u64 a, u64 b) {
    u64 d; asm("mul.rn.f32x2 %0, %1, %2;" : "=l"(d) : "l"(a), "l"(b)); return d;
}
__device__ __forceinline__ unsigned s2u(const void* p) {
    unsigned a;
    asm("{ .reg .u64 t; cvta.to.shared.u64 t, %1; cvt.u32.u64 %0, t; }" : "=r"(a) : "l"(p));
    return a;
}
// ---- MUFU approx helpers ----
__device__ __forceinline__ float sqrt_ap(float x){ float r; asm("sqrt.approx.f32 %0, %1;" : "=f"(r) : "f"(x)); return r; }
__device__ __forceinline__ float rcp_ap (float x){ float r; asm("rcp.approx.f32 %0, %1;"  : "=f"(r) : "f"(x)); return r; }
__device__ __forceinline__ float lg2_ap (float x){ float r; asm("lg2.approx.f32 %0, %1;"  : "=f"(r) : "f"(x)); return r; }
__device__ __forceinline__ float ex2_ap (float x){ float r; asm("ex2.approx.f32 %0, %1;"  : "=f"(r) : "f"(x)); return r; }

#define TILE_BYTES (NPT * DIM * 4)   // 66560, %16 == 0

__global__ __launch_bounds__(NPT, 2)
void hfh_kernel(const float* __restrict__ hyp, const float* __restrict__ anchors,
                float* __restrict__ out, int B)
{
    extern __shared__ float smem[];
    float* tile = smem;                       // NPT*DIM floats, row stride 65 (conflict-free)
    float* anch = smem + NPT * DIM;           // NA*ASTR floats: [s0..s63, a_t, -a_t, pad, pad]
    u64*   mbar = (u64*)(smem + NPT * DIM + NA * ASTR);

    const int tid = threadIdx.x;
    const long long p0 = (long long)blockIdx.x * NPT;
    const int n = min(NPT, B - (int)p0);
    const bool full = (n == NPT);
    const unsigned tile_sm = s2u(tile);
    const unsigned mbar_sm = s2u(mbar);

    // ---- Start async tile load (full blocks) ----
    if (full) {
        if (tid == 0) {
            asm volatile("mbarrier.init.shared.b64 [%0], %1;" :: "r"(mbar_sm), "r"(1) : "memory");
        }
        __syncthreads();
        if (tid == 0) {
            asm volatile("mbarrier.arrive.expect_tx.shared.b64 _, [%0], %1;"
                         :: "r"(mbar_sm), "r"(TILE_BYTES) : "memory");
            asm volatile("cp.async.bulk.shared::cta.global.mbarrier::complete_tx::bytes "
                         "[%0], [%1], %2, [%3];"
                         :: "r"(tile_sm), "l"(hyp + p0 * DIM), "r"(TILE_BYTES), "r"(mbar_sm)
                         : "memory");
        }
    } else {
        const float* src = hyp + p0 * DIM;
        for (int i = tid; i < n * DIM; i += NPT) tile[i] = src[i];
    }

    // ---- Anchor prep overlapped with the TMA load ----
    if (tid < NA) {
        float* ar = anch + tid * ASTR;
        const float* ga = anchors + tid * DIM + 1;
        float ss = 0.f;
        #pragma unroll
        for (int k = 0; k < 64; k++) { float v = ga[k]; ar[k] = v; ss = fmaf(v, v, ss); }
        float at = sqrtf(1.0f + ss);
        ar[64] = at; ar[65] = -at; ar[66] = 0.f; ar[67] = 0.f;
    }
    __syncthreads();                           // anchors (and scalar-path tile) visible

    if (full) {                                // wait for bulk tile
        asm volatile(
            "{\n\t.reg .pred P;\n\t"
            "WL_%=:\n\t"
            "mbarrier.try_wait.parity.acquire.cta.shared::cta.b64 P, [%0], 0, 0x989680;\n\t"
            "@P bra.uni WD_%=;\n\t"
            "bra.uni WL_%=;\n\t"
            "WD_%=:\n\t}"
            :: "r"(mbar_sm) : "memory");
    }

    if (tid < n) {
        float* row = tile + tid * DIM;
        const float h0 = row[0];
        u64 hp[32];
        #pragma unroll
        for (int j = 0; j < 32; j++) hp[j] = pk(row[1 + 2 * j], row[2 + 2 * j]);

        // ---- 16 Minkowski inners; first-min over clamped z == reference argmin ----
        float best_z = 3.4e38f, best_inner = 0.f;
        int best_a = 0;
        #pragma unroll 4
        for (int a = 0; a < NA; a++) {
            const float* base = anch + a * ASTR;
            const ulonglong2* av = (const ulonglong2*)base;
            u64 acc0 = pk(h0 * base[65], 0.f);          // seed with -h0*a_t
            u64 acc1 = pk(0.f, 0.f), acc2 = acc1, acc3 = acc1;
            #pragma unroll
            for (int j = 0; j < 16; j += 2) {
                ulonglong2 v0 = av[j];
                ulonglong2 v1 = av[j + 1];
                acc0 = ffma2(hp[2 * j],     v0.x, acc0);
                acc1 = ffma2(hp[2 * j + 1], v0.y, acc1);
                acc2 = ffma2(hp[2 * j + 2], v1.x, acc2);
                acc3 = ffma2(hp[2 * j + 3], v1.y, acc3);
            }
            float a0, a1, b0, b1, c0, c1x, d0, d1;
            upk(acc0, a0, a1); upk(acc1, b0, b1); upk(acc2, c0, c1x); upk(acc3, d0, d1);
            float inner = ((a0 + a1) + (b0 + b1)) + ((c0 + c1x) + (d0 + d1));
            float z = fmaxf(-inner, 1.0f + EPSF);
            if (z < best_z) { best_z = z; best_inner = inner; best_a = a; }
        }

        // ---- Epilogue: all-MUFU scalar chain ----
        // uu = linner(u,u) = xy^2 - 1 (hyperboloid identity); acosh(z) = ln(z + unorm)
        const float xy = best_inner;
        const float zc = best_z;
        const float* bb = anch + best_a * ASTR;
        const ulonglong2* av = (const ulonglong2*)bb;
        const float at = bb[64];

        float uu    = fmaf(xy, xy, -1.0f);
        float w     = sqrt_ap(fmaxf(uu, EPSF));               // unorm
        float d     = 0.69314718056f * lg2_ap(zc + w);        // acosh(zc)
        float scale = (ALPHA * d) * rcp_ap(w);
        float vv    = scale * scale * uu;
        float vn    = sqrt_ap(fmaxf(vv, EPSF * EPSF));
        float e     = ex2_ap(vn * 1.44269504089f);            // exp(vn)
        float ei    = rcp_ap(e);
        float ch    = 0.5f * (e + ei);
        float sh    = 0.5f * (e - ei);
        float rvn   = rcp_ap(vn);
        float sinhc = (vn > EPSF) ? sh * rvn : 1.0f;
        float s2    = sinhc * scale;
        float c1    = fmaf(s2, xy, ch);                       // out = c1*h + s2*na

        row[0] = fmaf(c1, h0, s2 * at);
        u64 c1v = pk(c1, c1), s2v = pk(s2, s2);
        #pragma unroll
        for (int j = 0; j < 16; j++) {
            ulonglong2 v = av[j];
            u64 oL = ffma2(c1v, hp[2 * j],     fmul2(s2v, v.x));
            u64 oH = ffma2(c1v, hp[2 * j + 1], fmul2(s2v, v.y));
            float a0, a1, b0, b1; upk(oL, a0, a1); upk(oH, b0, b1);
            row[1 + 4 * j] = a0; row[2 + 4 * j] = a1;
            row[3 + 4 * j] = b0; row[4 + 4 * j] = b1;
        }
    }
    __syncthreads();

    // ---- Bulk writeout ----
    if (full) {
        if (tid == 0) {
            asm volatile("fence.proxy.async.shared::cta;" ::: "memory");
            asm volatile("cp.async.bulk.global.shared::cta.bulk_group [%0], [%1], %2;"
                         :: "l"(out + p0 * DIM), "r"(tile_sm), "r"(TILE_BYTES) : "memory");
            asm volatile("cp.async.bulk.commit_group;" ::: "memory");
            asm volatile("cp.async.bulk.wait_group 0;" ::: "memory");
        }
    } else {
        float* dst = out + p0 * DIM;
        for (int i = tid; i < n * DIM; i += NPT) dst[i] = tile[i];
    }
}

extern "C" void kernel_launch(void* const* d_in, const int* in_sizes, int n_in,
                              void* d_out, int out_size)
{
    const float* hyp = (const float*)d_in[0];
    const float* anc = (const float*)d_in[1];
    float* out = (float*)d_out;
    const int B = in_sizes[0] / DIM;
    const int grid = (B + NPT - 1) / NPT;
    const size_t shmem = (size_t)(NPT * DIM + NA * ASTR) * sizeof(float) + 16;
    cudaFuncSetAttribute(hfh_kernel, cudaFuncAttributeMaxDynamicSharedMemorySize, (int)shmem);
    hfh_kernel<<<grid, NPT, shmem>>>(hyp, anc, out, B);
}

// round 8
// speedup vs baseline: 1.6074x; 1.1707x over previous
#include <cuda_runtime.h>

#define NTHR  128      // threads per block
#define NPT   256      // points per block (2 per thread)
#define DIM   65
#define NA    16
#define ASTR  68
#define ALPHA 0.1f
#define EPSF  1e-7f

typedef unsigned long long u64;

// ---- f32x2 packed helpers (sm_103a) ----
__device__ __forceinline__ u64 pk(float lo, float hi) {
    u64 r; asm("mov.b64 %0, {%1,%2};" : "=l"(r) : "f"(lo), "f"(hi)); return r;
}
__device__ __forceinline__ void upk(u64 v, float& lo, float& hi) {
    asm("mov.b64 {%0,%1}, %2;" : "=f"(lo), "=f"(hi) : "l"(v));
}
__device__ __forceinline__ u64 ffma2(u64 a, u64 b, u64 c) {
    u64 d; asm("fma.rn.f32x2 %0, %1, %2, %3;" : "=l"(d) : "l"(a), "l"(b), "l"(c)); return d;
}
__device__ __forceinline__ u64 fmul2(u64 a, u64 b) {
    u64 d; asm("mul.rn.f32x2 %0, %1, %2;" : "=l"(d) : "l"(a), "l"(b)); return d;
}
__device__ __forceinline__ unsigned s2u(const void* p) {
    unsigned a;
    asm("{ .reg .u64 t; cvta.to.shared.u64 t, %1; cvt.u32.u64 %0, t; }" : "=r"(a) : "l"(p));
    return a;
}
// ---- MUFU approx helpers ----
__device__ __forceinline__ float sqrt_ap(float x){ float r; asm("sqrt.approx.f32 %0, %1;" : "=f"(r) : "f"(x)); return r; }
__device__ __forceinline__ float rcp_ap (float x){ float r; asm("rcp.approx.f32 %0, %1;"  : "=f"(r) : "f"(x)); return r; }
__device__ __forceinline__ float lg2_ap (float x){ float r; asm("lg2.approx.f32 %0, %1;"  : "=f"(r) : "f"(x)); return r; }
__device__ __forceinline__ float ex2_ap (float x){ float r; asm("ex2.approx.f32 %0, %1;"  : "=f"(r) : "f"(x)); return r; }

#define TILE_BYTES (NPT * DIM * 4)   // 66560, %16 == 0

// Argmin + scalar chain + vector writeback for one point.
__device__ __forceinline__ void finish_point(const u64* acc, float* row, float h0,
                                             const float* anch, bool valid)
{
    float best_z = 3.4e38f, best_inner = 0.f;
    int best_a = 0;
    #pragma unroll
    for (int a = 0; a < NA; a++) {
        float x0, x1; upk(acc[a], x0, x1);
        float inner = x0 + x1;
        float z = fmaxf(-inner, 1.0f + EPSF);
        if (z < best_z) { best_z = z; best_inner = inner; best_a = a; }
    }
    const float xy = best_inner, zc = best_z;
    const float* bb = anch + best_a * ASTR;
    const float at = bb[64];

    // uu = linner(u,u) = xy^2 - 1 (hyperboloid identity); acosh(z) = ln(z + sqrt(z^2-1))
    float uu    = fmaf(xy, xy, -1.0f);
    float w     = sqrt_ap(fmaxf(uu, EPSF));
    float d     = 0.69314718056f * lg2_ap(zc + w);
    float scale = (ALPHA * d) * rcp_ap(w);
    float vv    = scale * scale * uu;
    float vn    = sqrt_ap(fmaxf(vv, EPSF * EPSF));
    float e     = ex2_ap(vn * 1.44269504089f);
    float ei    = rcp_ap(e);
    float ch    = 0.5f * (e + ei);
    float sh    = 0.5f * (e - ei);
    float sinhc = (vn > EPSF) ? sh * rcp_ap(vn) : 1.0f;
    float s2    = sinhc * scale;
    float c1    = fmaf(s2, xy, ch);              // out = c1*h + s2*na

    if (valid) {
        row[0] = fmaf(c1, h0, s2 * at);
        u64 c1v = pk(c1, c1), s2v = pk(s2, s2);
        const ulonglong2* av = (const ulonglong2*)bb;
        #pragma unroll
        for (int q = 0; q < 16; q++) {
            ulonglong2 v = av[q];
            u64 hL = pk(row[1 + 4 * q], row[2 + 4 * q]);
            u64 hH = pk(row[3 + 4 * q], row[4 + 4 * q]);
            u64 oL = ffma2(c1v, hL, fmul2(s2v, v.x));
            u64 oH = ffma2(c1v, hH, fmul2(s2v, v.y));
            float a0, a1, b0, b1; upk(oL, a0, a1); upk(oH, b0, b1);
            row[1 + 4 * q] = a0; row[2 + 4 * q] = a1;
            row[3 + 4 * q] = b0; row[4 + 4 * q] = b1;
        }
    }
}

__global__ __launch_bounds__(NTHR, 3)
void hfh_kernel(const float* __restrict__ hyp, const float* __restrict__ anchors,
                float* __restrict__ out, int B)
{
    extern __shared__ float smem[];
    float* tile = smem;                       // NPT*DIM floats, row stride 65 (conflict-free)
    float* anch = smem + NPT * DIM;           // NA*ASTR floats: [s0..s63, a_t, -a_t, pad, pad]
    u64*   mbar = (u64*)(smem + NPT * DIM + NA * ASTR);

    const int tid = threadIdx.x;
    const long long p0 = (long long)blockIdx.x * NPT;
    const int n = min(NPT, B - (int)p0);
    const bool full = (n == NPT);
    const unsigned tile_sm = s2u(tile);
    const unsigned mbar_sm = s2u(mbar);

    // ---- Start async tile load (full blocks) ----
    if (full) {
        if (tid == 0) {
            asm volatile("mbarrier.init.shared.b64 [%0], %1;" :: "r"(mbar_sm), "r"(1) : "memory");
        }
        __syncthreads();
        if (tid == 0) {
            asm volatile("mbarrier.arrive.expect_tx.shared.b64 _, [%0], %1;"
                         :: "r"(mbar_sm), "r"(TILE_BYTES) : "memory");
            asm volatile("cp.async.bulk.shared::cta.global.mbarrier::complete_tx::bytes "
                         "[%0], [%1], %2, [%3];"
                         :: "r"(tile_sm), "l"(hyp + p0 * DIM), "r"(TILE_BYTES), "r"(mbar_sm)
                         : "memory");
        }
    } else {
        const float* src = hyp + p0 * DIM;
        for (int i = tid; i < n * DIM; i += NTHR) tile[i] = src[i];
    }

    // ---- Anchor prep overlapped with the TMA load ----
    if (tid < NA) {
        float* ar = anch + tid * ASTR;
        const float* ga = anchors + tid * DIM + 1;
        float ss = 0.f;
        #pragma unroll
        for (int k = 0; k < 64; k++) { float v = ga[k]; ar[k] = v; ss = fmaf(v, v, ss); }
        float at = sqrtf(1.0f + ss);
        ar[64] = at; ar[65] = -at; ar[66] = 0.f; ar[67] = 0.f;
    }
    __syncthreads();

    if (full) {
        asm volatile(
            "{\n\t.reg .pred P;\n\t"
            "WL_%=:\n\t"
            "mbarrier.try_wait.parity.acquire.cta.shared::cta.b64 P, [%0], 0, 0x989680;\n\t"
            "@P bra.uni WD_%=;\n\t"
            "bra.uni WL_%=;\n\t"
            "WD_%=:\n\t}"
            :: "r"(mbar_sm) : "memory");
    }

    // ---- 2 points per thread ----
    const bool vA = tid < n;
    const bool vB = (tid + NTHR) < n;
    float* rowA = vA ? (tile + tid * DIM) : tile;             // invalid -> row 0 (finite dummy)
    float* rowB = vB ? (tile + (tid + NTHR) * DIM) : tile;
    const float h0A = rowA[0];
    const float h0B = rowB[0];

    u64 accA[NA], accB[NA];
    #pragma unroll
    for (int a = 0; a < NA; a++) {
        float atn = anch[a * ASTR + 65];                      // -a_t (broadcast)
        accA[a] = pk(h0A * atn, 0.f);
        accB[a] = pk(h0B * atn, 0.f);
    }

    // Anchor FMA loop in two 32-dim chunks; each anchor LDS.128 feeds 4 ffma2.
    #pragma unroll
    for (int c = 0; c < 2; c++) {
        u64 hA[16], hB[16];
        const float* ra = rowA + 1 + 32 * c;
        const float* rb = rowB + 1 + 32 * c;
        #pragma unroll
        for (int j = 0; j < 16; j++) {
            hA[j] = pk(ra[2 * j], ra[2 * j + 1]);
            hB[j] = pk(rb[2 * j], rb[2 * j + 1]);
        }
        #pragma unroll
        for (int a = 0; a < NA; a++) {
            const ulonglong2* av = (const ulonglong2*)(anch + a * ASTR) + 8 * c;
            #pragma unroll
            for (int q = 0; q < 8; q++) {
                ulonglong2 v = av[q];                         // broadcast LDS.128
                accA[a] = ffma2(hA[2 * q],     v.x, accA[a]);
                accA[a] = ffma2(hA[2 * q + 1], v.y, accA[a]);
                accB[a] = ffma2(hB[2 * q],     v.x, accB[a]);
                accB[a] = ffma2(hB[2 * q + 1], v.y, accB[a]);
            }
        }
    }

    finish_point(accA, rowA, h0A, anch, vA);
    finish_point(accB, rowB, h0B, anch, vB);

    __syncthreads();

    // ---- Bulk writeout ----
    if (full) {
        if (tid == 0) {
            asm volatile("fence.proxy.async.shared::cta;" ::: "memory");
            asm volatile("cp.async.bulk.global.shared::cta.bulk_group [%0], [%1], %2;"
                         :: "l"(out + p0 * DIM), "r"(tile_sm), "r"(TILE_BYTES) : "memory");
            asm volatile("cp.async.bulk.commit_group;" ::: "memory");
            asm volatile("cp.async.bulk.wait_group 0;" ::: "memory");
        }
    } else {
        float* dst = out + p0 * DIM;
        for (int i = tid; i < n * DIM; i += NTHR) dst[i] = tile[i];
    }
}

extern "C" void kernel_launch(void* const* d_in, const int* in_sizes, int n_in,
                              void* d_out, int out_size)
{
    const float* hyp = (const float*)d_in[0];
    const float* anc = (const float*)d_in[1];
    float* out = (float*)d_out;
    const int B = in_sizes[0] / DIM;
    const int grid = (B + NPT - 1) / NPT;
    const size_t shmem = (size_t)(NPT * DIM + NA * ASTR) * sizeof(float) + 16;
    cudaFuncSetAttribute(hfh_kernel, cudaFuncAttributeMaxDynamicSharedMemorySize, (int)shmem);
    hfh_kernel<<<grid, NTHR, shmem>>>(hyp, anc, out, B);
}